// round 1
// baseline (speedup 1.0000x reference)
#include <cuda_runtime.h>
#include <math.h>

#define NB    4
#define T     4096
#define DIN   1024
#define DHEAD 64
#define MT    (NB*T)   /* 16384 rows */

// Scratch for Q,K,V (static device arrays: allocation-free per harness rules)
__device__ float g_q[MT*DHEAD];
__device__ float g_k[MT*DHEAD];
__device__ float g_v[MT*DHEAD];

// ---------------------------------------------------------------------------
// Kernel 1: fused QKV projection.  out = relu(x @ W^T + b)
// grid (3, MT/128), block 256. Tile: 128 rows x 64 cols, K-chunk 32.
// Thread micro-tile: 8 rows x 4 cols  (2.7 FMA per shared load)
// ---------------------------------------------------------------------------
#define BM 128
#define BK 32

__global__ __launch_bounds__(256) void qkv_kernel(
    const float* __restrict__ x,
    const float* __restrict__ Wk, const float* __restrict__ bk,
    const float* __restrict__ Wq, const float* __restrict__ bq,
    const float* __restrict__ Wv, const float* __restrict__ bv)
{
    __shared__ float xs[BK][BM+4];    // [k][m], padded
    __shared__ float ws[BK][DHEAD];   // [k][n], 256B row pitch (float4-aligned)

    const int mat = blockIdx.x;
    const float* W; const float* bias; float* out;
    if (mat == 0)      { W = Wk; bias = bk; out = g_k; }
    else if (mat == 1) { W = Wq; bias = bq; out = g_q; }
    else               { W = Wv; bias = bv; out = g_v; }

    const int m0  = blockIdx.y * BM;
    const int tid = threadIdx.x;
    const int ty  = tid >> 4;   // 0..15 -> 8 rows each
    const int tx  = tid & 15;   // 0..15 -> 4 cols each

    float acc[8][4];
    #pragma unroll
    for (int r = 0; r < 8; r++)
        #pragma unroll
        for (int c = 0; c < 4; c++) acc[r][c] = 0.f;

    for (int kc = 0; kc < DIN; kc += BK) {
        // x tile: 128x32 -> transposed into xs[k][m]   (1024 float4 / 256 thr)
        #pragma unroll
        for (int i = 0; i < 4; i++) {
            int idx = tid + 256*i;
            int row = idx >> 3;
            int j   = idx & 7;
            float4 v = *(const float4*)&x[(size_t)(m0+row)*DIN + kc + j*4];
            xs[j*4+0][row] = v.x; xs[j*4+1][row] = v.y;
            xs[j*4+2][row] = v.z; xs[j*4+3][row] = v.w;
        }
        // W tile: 64x32 -> transposed into ws[k][n]    (512 float4 / 256 thr)
        #pragma unroll
        for (int i = 0; i < 2; i++) {
            int idx = tid + 256*i;
            int row = idx >> 3;
            int j   = idx & 7;
            float4 v = *(const float4*)&W[(size_t)row*DIN + kc + j*4];
            ws[j*4+0][row] = v.x; ws[j*4+1][row] = v.y;
            ws[j*4+2][row] = v.z; ws[j*4+3][row] = v.w;
        }
        __syncthreads();

        #pragma unroll
        for (int kk = 0; kk < BK; kk++) {
            float4 wv = *(const float4*)&ws[kk][tx*4];
            float xv[8];
            #pragma unroll
            for (int r = 0; r < 8; r++) xv[r] = xs[kk][ty*8+r];
            #pragma unroll
            for (int r = 0; r < 8; r++) {
                acc[r][0] = fmaf(xv[r], wv.x, acc[r][0]);
                acc[r][1] = fmaf(xv[r], wv.y, acc[r][1]);
                acc[r][2] = fmaf(xv[r], wv.z, acc[r][2]);
                acc[r][3] = fmaf(xv[r], wv.w, acc[r][3]);
            }
        }
        __syncthreads();
    }

    float4 bb = *(const float4*)&bias[tx*4];
    #pragma unroll
    for (int r = 0; r < 8; r++) {
        float4 o;
        o.x = fmaxf(acc[r][0] + bb.x, 0.f);
        o.y = fmaxf(acc[r][1] + bb.y, 0.f);
        o.z = fmaxf(acc[r][2] + bb.z, 0.f);
        o.w = fmaxf(acc[r][3] + bb.w, 0.f);
        *(float4*)&out[(size_t)(m0 + ty*8 + r)*DHEAD + tx*4] = o;
    }
}

// ---------------------------------------------------------------------------
// Kernel 2: flash attention, fp32, online softmax.
// grid (T/64, B), block 128 (ty 0..7 -> 8 queries, tx 0..15 -> 4 keys/4 dims)
// Tiles: 64 queries x 64 keys. Dynamic smem: Qs,KsT,Vs,Ps @ pitch 68.
// ---------------------------------------------------------------------------
#define AQ 64
#define AK 64
#define PITCH 68   // 272B rows: float4-aligned, bank-conflict-light
#define ATTN_SMEM (4 * AQ * PITCH * sizeof(float))   // 69632 bytes

__global__ __launch_bounds__(128) void attn_kernel(float* __restrict__ out)
{
    extern __shared__ float sm[];
    float* Qs  = sm;                   // [q][d]   (pre-scaled by 1/8)
    float* KsT = Qs  + AQ*PITCH;       // [d][k]
    float* Vs  = KsT + DHEAD*PITCH;    // [k][d]
    float* Ps  = Vs  + AK*PITCH;       // [q][k]

    const int b   = blockIdx.y;
    const int q0  = blockIdx.x * AQ;
    const int tid = threadIdx.x;
    const int ty  = tid >> 4;   // 0..7
    const int tx  = tid & 15;   // 0..15

    const float* Qg = g_q + ((size_t)b*T + q0)*DHEAD;
    const float* Kg = g_k + (size_t)b*T*DHEAD;
    const float* Vg = g_v + (size_t)b*T*DHEAD;

    const float scale = 0.125f;  // 1/sqrt(64)

    // Load + pre-scale Q tile (1024 float4 / 128 thr)
    #pragma unroll
    for (int i = 0; i < 8; i++) {
        int idx = tid + 128*i;
        int row = idx >> 4;
        int j   = idx & 15;
        float4 v = *(const float4*)&Qg[row*DHEAD + j*4];
        v.x *= scale; v.y *= scale; v.z *= scale; v.w *= scale;
        *(float4*)&Qs[row*PITCH + j*4] = v;
    }

    float m[8], l[8], o[8][4];
    #pragma unroll
    for (int qq = 0; qq < 8; qq++) {
        m[qq] = -1e30f; l[qq] = 0.f;
        #pragma unroll
        for (int c = 0; c < 4; c++) o[qq][c] = 0.f;
    }

    for (int kt = 0; kt < T; kt += AK) {
        __syncthreads();   // protect Vs/Ps of previous iteration
        // Load K (transposed) and V tiles
        #pragma unroll
        for (int i = 0; i < 8; i++) {
            int idx = tid + 128*i;
            int row = idx >> 4;
            int j   = idx & 15;
            float4 kv = *(const float4*)&Kg[(size_t)(kt+row)*DHEAD + j*4];
            KsT[(j*4+0)*PITCH + row] = kv.x;
            KsT[(j*4+1)*PITCH + row] = kv.y;
            KsT[(j*4+2)*PITCH + row] = kv.z;
            KsT[(j*4+3)*PITCH + row] = kv.w;
            float4 vv = *(const float4*)&Vg[(size_t)(kt+row)*DHEAD + j*4];
            *(float4*)&Vs[row*PITCH + j*4] = vv;
        }
        __syncthreads();

        // Scores: s[qq][kk] = sum_d Qs[q][d] * KsT[d][k]
        float s[8][4];
        #pragma unroll
        for (int qq = 0; qq < 8; qq++)
            #pragma unroll
            for (int kk = 0; kk < 4; kk++) s[qq][kk] = 0.f;

        #pragma unroll
        for (int d = 0; d < DHEAD; d += 4) {
            float4 kv0 = *(const float4*)&KsT[(d+0)*PITCH + tx*4];
            float4 kv1 = *(const float4*)&KsT[(d+1)*PITCH + tx*4];
            float4 kv2 = *(const float4*)&KsT[(d+2)*PITCH + tx*4];
            float4 kv3 = *(const float4*)&KsT[(d+3)*PITCH + tx*4];
            #pragma unroll
            for (int qq = 0; qq < 8; qq++) {
                float4 qv = *(const float4*)&Qs[(ty*8+qq)*PITCH + d];
                s[qq][0] = fmaf(qv.x, kv0.x, fmaf(qv.y, kv1.x, fmaf(qv.z, kv2.x, fmaf(qv.w, kv3.x, s[qq][0]))));
                s[qq][1] = fmaf(qv.x, kv0.y, fmaf(qv.y, kv1.y, fmaf(qv.z, kv2.y, fmaf(qv.w, kv3.y, s[qq][1]))));
                s[qq][2] = fmaf(qv.x, kv0.z, fmaf(qv.y, kv1.z, fmaf(qv.z, kv2.z, fmaf(qv.w, kv3.z, s[qq][2]))));
                s[qq][3] = fmaf(qv.x, kv0.w, fmaf(qv.y, kv1.w, fmaf(qv.z, kv2.w, fmaf(qv.w, kv3.w, s[qq][3]))));
            }
        }

        // Online softmax update (per query row; 16 tx lanes hold replicas)
        #pragma unroll
        for (int qq = 0; qq < 8; qq++) {
            float mx = fmaxf(fmaxf(s[qq][0], s[qq][1]), fmaxf(s[qq][2], s[qq][3]));
            #pragma unroll
            for (int off = 1; off < 16; off <<= 1)
                mx = fmaxf(mx, __shfl_xor_sync(0xffffffffu, mx, off));
            float mnew  = fmaxf(m[qq], mx);
            float alpha = __expf(m[qq] - mnew);
            float p0 = __expf(s[qq][0] - mnew);
            float p1 = __expf(s[qq][1] - mnew);
            float p2 = __expf(s[qq][2] - mnew);
            float p3 = __expf(s[qq][3] - mnew);
            float ps = (p0 + p1) + (p2 + p3);
            #pragma unroll
            for (int off = 1; off < 16; off <<= 1)
                ps += __shfl_xor_sync(0xffffffffu, ps, off);
            l[qq] = l[qq]*alpha + ps;
            m[qq] = mnew;
            o[qq][0] *= alpha; o[qq][1] *= alpha; o[qq][2] *= alpha; o[qq][3] *= alpha;
            float4 pv = make_float4(p0, p1, p2, p3);
            *(float4*)&Ps[(ty*8+qq)*PITCH + tx*4] = pv;
        }
        __syncthreads();

        // o[qq][c] += sum_k Ps[q][k] * Vs[k][tx*4+c]
        #pragma unroll 8
        for (int k = 0; k < AK; k++) {
            float4 vv = *(const float4*)&Vs[k*PITCH + tx*4];
            #pragma unroll
            for (int qq = 0; qq < 8; qq++) {
                float p = Ps[(ty*8+qq)*PITCH + k];
                o[qq][0] = fmaf(p, vv.x, o[qq][0]);
                o[qq][1] = fmaf(p, vv.y, o[qq][1]);
                o[qq][2] = fmaf(p, vv.z, o[qq][2]);
                o[qq][3] = fmaf(p, vv.w, o[qq][3]);
            }
        }
    }

    float* Og = out + ((size_t)b*T + q0)*DHEAD;
    #pragma unroll
    for (int qq = 0; qq < 8; qq++) {
        float inv = 1.f / l[qq];
        float4 ov = make_float4(o[qq][0]*inv, o[qq][1]*inv, o[qq][2]*inv, o[qq][3]*inv);
        *(float4*)&Og[(size_t)(ty*8+qq)*DHEAD + tx*4] = ov;
    }
}

// ---------------------------------------------------------------------------
extern "C" void kernel_launch(void* const* d_in, const int* in_sizes, int n_in,
                              void* d_out, int out_size)
{
    const float* x  = (const float*)d_in[0];
    const float* Wk = (const float*)d_in[1];
    const float* bk = (const float*)d_in[2];
    const float* Wq = (const float*)d_in[3];
    const float* bq = (const float*)d_in[4];
    const float* Wv = (const float*)d_in[5];
    const float* bv = (const float*)d_in[6];
    float* out = (float*)d_out;

    // Opt-in to >48KB dynamic smem (host-side attribute; not a stream op,
    // safe under graph capture; idempotent every call).
    cudaFuncSetAttribute(attn_kernel,
                         cudaFuncAttributeMaxDynamicSharedMemorySize,
                         (int)ATTN_SMEM);

    dim3 g1(3, MT / BM);
    qkv_kernel<<<g1, 256>>>(x, Wk, bk, Wq, bq, Wv, bv);

    dim3 g2(T / AQ, NB);
    attn_kernel<<<g2, 128, ATTN_SMEM>>>(out);
}

// round 2
// speedup vs baseline: 2.1841x; 2.1841x over previous
#include <cuda_runtime.h>
#include <cuda_bf16.h>
#include <math.h>

#define NB    4
#define T     4096
#define DIN   1024
#define DHEAD 64
#define MT    (NB*T)

#define P32   36          // smem pitch in u32 (72 bf16 = 144B): bank = 4g+q, conflict-free
#define WARPS 8

// Scratch for Q,K,V (fp32, row-major [MT][64])
__device__ float g_q[MT*DHEAD];
__device__ float g_k[MT*DHEAD];
__device__ float g_v[MT*DHEAD];

// ---------------------------------------------------------------------------
// helpers
// ---------------------------------------------------------------------------
__device__ __forceinline__ void mma16816(float&c0,float&c1,float&c2,float&c3,
                                         unsigned a0,unsigned a1,unsigned a2,unsigned a3,
                                         unsigned b0,unsigned b1)
{
    asm volatile("mma.sync.aligned.m16n8k16.row.col.f32.bf16.bf16.f32 "
        "{%0,%1,%2,%3},{%4,%5,%6,%7},{%8,%9},{%0,%1,%2,%3};"
        : "+f"(c0),"+f"(c1),"+f"(c2),"+f"(c3)
        : "r"(a0),"r"(a1),"r"(a2),"r"(a3),"r"(b0),"r"(b1));
}

// pack two floats (lo=even element, hi=odd element) into bf16x2 big + residual
__device__ __forceinline__ void split2(float lo, float hi, unsigned &b, unsigned &r)
{
    asm("cvt.rn.bf16x2.f32 %0, %1, %2;" : "=r"(b) : "f"(hi), "f"(lo));
    __nv_bfloat162 h2 = *reinterpret_cast<__nv_bfloat162*>(&b);
    float blo = __bfloat162float(h2.x);
    float bhi = __bfloat162float(h2.y);
    asm("cvt.rn.bf16x2.f32 %0, %1, %2;" : "=r"(r) : "f"(hi-bhi), "f"(lo-blo));
}

__device__ __forceinline__ unsigned pack2(float lo, float hi)
{
    unsigned d;
    asm("cvt.rn.bf16x2.f32 %0, %1, %2;" : "=r"(d) : "f"(hi), "f"(lo));
    return d;
}

__device__ __forceinline__ void split1(float x, unsigned short &b, unsigned short &r)
{
    __nv_bfloat16 hb = __float2bfloat16(x);
    b = __bfloat16_as_ushort(hb);
    r = __bfloat16_as_ushort(__float2bfloat16(x - __bfloat162float(hb)));
}

// ---------------------------------------------------------------------------
// Kernel 1: QKV projection with split-bf16 mma.  out = relu(x @ W^T + b)
// grid (3 mats, MT/128), block 256 (8 warps, each 16 rows).
// ---------------------------------------------------------------------------
#define QKV_SMEM ((128*2 + 64*2) * P32 * 4)   // Xb,Xr,Wb,Wr = 55296 B

__global__ __launch_bounds__(256) void qkv_kernel(
    const float* __restrict__ x,
    const float* __restrict__ Wk, const float* __restrict__ bk,
    const float* __restrict__ Wq, const float* __restrict__ bq,
    const float* __restrict__ Wv, const float* __restrict__ bv)
{
    extern __shared__ unsigned smu[];
    unsigned* Xb = smu;
    unsigned* Xr = Xb + 128*P32;
    unsigned* Wb = Xr + 128*P32;
    unsigned* Wr = Wb + 64*P32;

    const int mat = blockIdx.x;
    const float* W; const float* bias; float* out;
    if (mat == 0)      { W = Wk; bias = bk; out = g_k; }
    else if (mat == 1) { W = Wq; bias = bq; out = g_q; }
    else               { W = Wv; bias = bv; out = g_v; }

    const int m0   = blockIdx.y * 128;
    const int tid  = threadIdx.x;
    const int w    = tid >> 5;
    const int lane = tid & 31;
    const int g    = lane >> 2;   // groupID
    const int q    = lane & 3;    // thread in group
    const int wrow = w * 16;

    float acc[8][4];
    #pragma unroll
    for (int j = 0; j < 8; j++)
        #pragma unroll
        for (int c = 0; c < 4; c++) acc[j][c] = 0.f;

    for (int kc = 0; kc < DIN; kc += 64) {
        __syncthreads();
        // X tile: 128 rows x 64 dims
        #pragma unroll
        for (int i = 0; i < 8; i++) {
            int idx = tid + 256*i;
            int row = idx >> 4, c4 = idx & 15;
            float4 v = *(const float4*)&x[(size_t)(m0+row)*DIN + kc + c4*4];
            unsigned b0,r0,b1,r1;
            split2(v.x, v.y, b0, r0);
            split2(v.z, v.w, b1, r1);
            Xb[row*P32 + c4*2    ] = b0;  Xb[row*P32 + c4*2 + 1] = b1;
            Xr[row*P32 + c4*2    ] = r0;  Xr[row*P32 + c4*2 + 1] = r1;
        }
        // W tile: 64 rows x 64 dims
        #pragma unroll
        for (int i = 0; i < 4; i++) {
            int idx = tid + 256*i;
            int row = idx >> 4, c4 = idx & 15;
            float4 v = *(const float4*)&W[(size_t)row*DIN + kc + c4*4];
            unsigned b0,r0,b1,r1;
            split2(v.x, v.y, b0, r0);
            split2(v.z, v.w, b1, r1);
            Wb[row*P32 + c4*2    ] = b0;  Wb[row*P32 + c4*2 + 1] = b1;
            Wr[row*P32 + c4*2    ] = r0;  Wr[row*P32 + c4*2 + 1] = r1;
        }
        __syncthreads();

        #pragma unroll
        for (int ks = 0; ks < 4; ks++) {
            const int ab = (wrow+g)*P32 + ks*8 + q;
            unsigned xb0 = Xb[ab],        xb1 = Xb[ab + 8*P32];
            unsigned xb2 = Xb[ab + 4],    xb3 = Xb[ab + 8*P32 + 4];
            unsigned xr0 = Xr[ab],        xr1 = Xr[ab + 8*P32];
            unsigned xr2 = Xr[ab + 4],    xr3 = Xr[ab + 8*P32 + 4];
            #pragma unroll
            for (int jn = 0; jn < 8; jn++) {
                const int bb = (jn*8+g)*P32 + ks*8 + q;
                unsigned wb0 = Wb[bb], wb1 = Wb[bb+4];
                unsigned wr0 = Wr[bb], wr1 = Wr[bb+4];
                mma16816(acc[jn][0],acc[jn][1],acc[jn][2],acc[jn][3], xb0,xb1,xb2,xb3, wb0,wb1);
                mma16816(acc[jn][0],acc[jn][1],acc[jn][2],acc[jn][3], xb0,xb1,xb2,xb3, wr0,wr1);
                mma16816(acc[jn][0],acc[jn][1],acc[jn][2],acc[jn][3], xr0,xr1,xr2,xr3, wb0,wb1);
            }
        }
    }

    // epilogue: bias + relu, fp32 store
    #pragma unroll
    for (int jn = 0; jn < 8; jn++) {
        int col = jn*8 + q*2;
        float2 bb = *(const float2*)&bias[col];
        int r0 = m0 + wrow + g;
        float2 o0 = make_float2(fmaxf(acc[jn][0]+bb.x,0.f), fmaxf(acc[jn][1]+bb.y,0.f));
        float2 o1 = make_float2(fmaxf(acc[jn][2]+bb.x,0.f), fmaxf(acc[jn][3]+bb.y,0.f));
        *(float2*)&out[(size_t)r0*DHEAD + col]     = o0;
        *(float2*)&out[(size_t)(r0+8)*DHEAD + col] = o1;
    }
}

// ---------------------------------------------------------------------------
// Kernel 2: flash attention with split-bf16 mma.
// grid (T/128, B), block 256 (8 warps x 16 q-rows = 128 q per CTA), AK=64.
// ---------------------------------------------------------------------------
#define ATTN_SMEM ((128*2 + 64*4) * P32 * 4)   // Qb,Qr,Kb,Kr,Vb,Vr = 73728 B

__global__ __launch_bounds__(256) void attn_kernel(float* __restrict__ out)
{
    extern __shared__ unsigned smu[];
    unsigned* Qb = smu;                 // [128][P32]  (pre-scaled by 1/8)
    unsigned* Qr = Qb + 128*P32;
    unsigned* Kb = Qr + 128*P32;        // [64 keys][P32]  (dims in pairs)
    unsigned* Kr = Kb + 64*P32;
    unsigned* Vb = Kr + 64*P32;         // transposed: bf16 [64 dims][72 keys]
    unsigned* Vr = Vb + 64*P32;
    unsigned short* Vb16 = (unsigned short*)Vb;
    unsigned short* Vr16 = (unsigned short*)Vr;

    const int b    = blockIdx.y;
    const int q0   = blockIdx.x * 128;
    const int tid  = threadIdx.x;
    const int w    = tid >> 5;
    const int lane = tid & 31;
    const int g    = lane >> 2;
    const int q    = lane & 3;
    const int wrow = w * 16;

    const float* Qg = g_q + ((size_t)b*T + q0)*DHEAD;
    const float* Kg = g_k + (size_t)b*T*DHEAD;
    const float* Vg = g_v + (size_t)b*T*DHEAD;
    const float scale = 0.125f;

    // Load + scale + split Q tile (128 x 64)
    #pragma unroll
    for (int i = 0; i < 8; i++) {
        int idx = tid + 256*i;
        int row = idx >> 4, c4 = idx & 15;
        float4 v = *(const float4*)&Qg[row*DHEAD + c4*4];
        v.x*=scale; v.y*=scale; v.z*=scale; v.w*=scale;
        unsigned b0,r0,b1,r1;
        split2(v.x, v.y, b0, r0);
        split2(v.z, v.w, b1, r1);
        Qb[row*P32 + c4*2] = b0;  Qb[row*P32 + c4*2 + 1] = b1;
        Qr[row*P32 + c4*2] = r0;  Qr[row*P32 + c4*2 + 1] = r1;
    }

    float oacc[8][4];
    #pragma unroll
    for (int j = 0; j < 8; j++)
        #pragma unroll
        for (int c = 0; c < 4; c++) oacc[j][c] = 0.f;
    float m0 = -1e30f, m1 = -1e30f, l0 = 0.f, l1 = 0.f;

    for (int kt = 0; kt < T; kt += 64) {
        __syncthreads();   // protect previous tile's K/V
        // Load K (row-major pairs) and V (transposed) tiles, 64 x 64 each
        #pragma unroll
        for (int i = 0; i < 4; i++) {
            int idx = tid + 256*i;
            int row = idx >> 4, c4 = idx & 15;
            float4 kv = *(const float4*)&Kg[(size_t)(kt+row)*DHEAD + c4*4];
            unsigned kb0,kr0,kb1,kr1;
            split2(kv.x, kv.y, kb0, kr0);
            split2(kv.z, kv.w, kb1, kr1);
            Kb[row*P32 + c4*2] = kb0;  Kb[row*P32 + c4*2 + 1] = kb1;
            Kr[row*P32 + c4*2] = kr0;  Kr[row*P32 + c4*2 + 1] = kr1;

            float4 vv = *(const float4*)&Vg[(size_t)(kt+row)*DHEAD + c4*4];
            #pragma unroll
            for (int e = 0; e < 4; e++) {
                float f = (e==0)?vv.x:(e==1)?vv.y:(e==2)?vv.z:vv.w;
                unsigned short vb, vr;
                split1(f, vb, vr);
                int d = c4*4 + e;
                Vb16[d*(2*P32) + row] = vb;
                Vr16[d*(2*P32) + row] = vr;
            }
        }
        __syncthreads();

        // S = Q K^T  (split: bb + br + rb)
        float s[8][4];
        #pragma unroll
        for (int j = 0; j < 8; j++)
            #pragma unroll
            for (int c = 0; c < 4; c++) s[j][c] = 0.f;

        #pragma unroll
        for (int ks = 0; ks < 4; ks++) {
            const int ab = (wrow+g)*P32 + ks*8 + q;
            unsigned qb0 = Qb[ab],     qb1 = Qb[ab + 8*P32];
            unsigned qb2 = Qb[ab + 4], qb3 = Qb[ab + 8*P32 + 4];
            unsigned qr0 = Qr[ab],     qr1 = Qr[ab + 8*P32];
            unsigned qr2 = Qr[ab + 4], qr3 = Qr[ab + 8*P32 + 4];
            #pragma unroll
            for (int jn = 0; jn < 8; jn++) {
                const int bb = (jn*8+g)*P32 + ks*8 + q;
                unsigned kb0 = Kb[bb], kb1 = Kb[bb+4];
                unsigned kr0 = Kr[bb], kr1 = Kr[bb+4];
                mma16816(s[jn][0],s[jn][1],s[jn][2],s[jn][3], qb0,qb1,qb2,qb3, kb0,kb1);
                mma16816(s[jn][0],s[jn][1],s[jn][2],s[jn][3], qb0,qb1,qb2,qb3, kr0,kr1);
                mma16816(s[jn][0],s[jn][1],s[jn][2],s[jn][3], qr0,qr1,qr2,qr3, kb0,kb1);
            }
        }

        // online softmax (rows g and g+8; 4 lanes per row within quad)
        float mx0 = -1e30f, mx1 = -1e30f;
        #pragma unroll
        for (int j = 0; j < 8; j++) {
            mx0 = fmaxf(mx0, fmaxf(s[j][0], s[j][1]));
            mx1 = fmaxf(mx1, fmaxf(s[j][2], s[j][3]));
        }
        mx0 = fmaxf(mx0, __shfl_xor_sync(0xffffffffu, mx0, 1));
        mx0 = fmaxf(mx0, __shfl_xor_sync(0xffffffffu, mx0, 2));
        mx1 = fmaxf(mx1, __shfl_xor_sync(0xffffffffu, mx1, 1));
        mx1 = fmaxf(mx1, __shfl_xor_sync(0xffffffffu, mx1, 2));
        float mn0 = fmaxf(m0, mx0), mn1 = fmaxf(m1, mx1);
        float al0 = __expf(m0 - mn0), al1 = __expf(m1 - mn1);
        m0 = mn0; m1 = mn1;

        float sum0 = 0.f, sum1 = 0.f;
        #pragma unroll
        for (int j = 0; j < 8; j++) {
            s[j][0] = __expf(s[j][0] - mn0);
            s[j][1] = __expf(s[j][1] - mn0);
            s[j][2] = __expf(s[j][2] - mn1);
            s[j][3] = __expf(s[j][3] - mn1);
            sum0 += s[j][0] + s[j][1];
            sum1 += s[j][2] + s[j][3];
        }
        sum0 += __shfl_xor_sync(0xffffffffu, sum0, 1);
        sum0 += __shfl_xor_sync(0xffffffffu, sum0, 2);
        sum1 += __shfl_xor_sync(0xffffffffu, sum1, 1);
        sum1 += __shfl_xor_sync(0xffffffffu, sum1, 2);
        l0 = l0*al0 + sum0;
        l1 = l1*al1 + sum1;
        #pragma unroll
        for (int j = 0; j < 8; j++) {
            oacc[j][0]*=al0; oacc[j][1]*=al0; oacc[j][2]*=al1; oacc[j][3]*=al1;
        }

        // O += P V   (P fragments come straight from s[][]; split P and V)
        #pragma unroll
        for (int kp = 0; kp < 4; kp++) {
            unsigned pb0,pr0,pb1,pr1,pb2,pr2,pb3,pr3;
            split2(s[2*kp  ][0], s[2*kp  ][1], pb0, pr0);
            split2(s[2*kp  ][2], s[2*kp  ][3], pb1, pr1);
            split2(s[2*kp+1][0], s[2*kp+1][1], pb2, pr2);
            split2(s[2*kp+1][2], s[2*kp+1][3], pb3, pr3);
            #pragma unroll
            for (int jn = 0; jn < 8; jn++) {
                const int vb = (jn*8+g)*P32 + kp*8 + q;
                unsigned vb0 = Vb[vb], vb1 = Vb[vb+4];
                unsigned vr0 = Vr[vb], vr1 = Vr[vb+4];
                mma16816(oacc[jn][0],oacc[jn][1],oacc[jn][2],oacc[jn][3], pb0,pb1,pb2,pb3, vb0,vb1);
                mma16816(oacc[jn][0],oacc[jn][1],oacc[jn][2],oacc[jn][3], pb0,pb1,pb2,pb3, vr0,vr1);
                mma16816(oacc[jn][0],oacc[jn][1],oacc[jn][2],oacc[jn][3], pr0,pr1,pr2,pr3, vb0,vb1);
            }
        }
    }

    float inv0 = 1.f / l0, inv1 = 1.f / l1;
    float* Og = out + ((size_t)b*T + q0)*DHEAD;
    #pragma unroll
    for (int jn = 0; jn < 8; jn++) {
        int col = jn*8 + q*2;
        int r0 = wrow + g;
        float2 o0 = make_float2(oacc[jn][0]*inv0, oacc[jn][1]*inv0);
        float2 o1 = make_float2(oacc[jn][2]*inv1, oacc[jn][3]*inv1);
        *(float2*)&Og[(size_t)r0*DHEAD + col]     = o0;
        *(float2*)&Og[(size_t)(r0+8)*DHEAD + col] = o1;
    }
}

// ---------------------------------------------------------------------------
extern "C" void kernel_launch(void* const* d_in, const int* in_sizes, int n_in,
                              void* d_out, int out_size)
{
    const float* x  = (const float*)d_in[0];
    const float* Wk = (const float*)d_in[1];
    const float* bk = (const float*)d_in[2];
    const float* Wq = (const float*)d_in[3];
    const float* bq = (const float*)d_in[4];
    const float* Wv = (const float*)d_in[5];
    const float* bv = (const float*)d_in[6];
    float* out = (float*)d_out;

    cudaFuncSetAttribute(qkv_kernel,
                         cudaFuncAttributeMaxDynamicSharedMemorySize, QKV_SMEM);
    cudaFuncSetAttribute(attn_kernel,
                         cudaFuncAttributeMaxDynamicSharedMemorySize, ATTN_SMEM);

    dim3 g1(3, MT / 128);
    qkv_kernel<<<g1, 256, QKV_SMEM>>>(x, Wk, bk, Wq, bq, Wv, bv);

    dim3 g2(T / 128, NB);
    attn_kernel<<<g2, 256, ATTN_SMEM>>>(out);
}

// round 3
// speedup vs baseline: 2.2244x; 1.0185x over previous
#include <cuda_runtime.h>
#include <cuda_bf16.h>

#define NB    4
#define T     4096
#define DIN   1024
#define DHEAD 64
#define MT    (NB*T)
#define PCH   40        // smem pitch in u32: 8g+2q bank pattern -> conflict-free LDS.64

// Pre-split bf16 planes, fragment-ordered (32 u32 per row of 64 values)
__device__ unsigned g_qb[MT*32], g_qr[MT*32];
__device__ unsigned g_kb[MT*32], g_kr[MT*32];
// V transposed: [b][dim 0..63][T/2 u32 key-pairs], fragment-ordered per 64-key tile
__device__ unsigned g_vtb[NB*64*(T/2)], g_vtr[NB*64*(T/2)];

// ---------------------------------------------------------------------------
// helpers
// ---------------------------------------------------------------------------
// slot of value-pair p (p = valueIndex/2) within a 32-u32 fragment-ordered row:
// pairs (8k+q, 8k+q+4) land adjacent -> LDS.64/LDG.64 yields (reg0, reg1)
__device__ __forceinline__ int slotf(int p) {
    return ((p >> 3) << 3) + ((p & 3) << 1) + ((p >> 2) & 1);
}

__device__ __forceinline__ void mma16816(float&c0,float&c1,float&c2,float&c3,
                                         unsigned a0,unsigned a1,unsigned a2,unsigned a3,
                                         unsigned b0,unsigned b1)
{
    asm volatile("mma.sync.aligned.m16n8k16.row.col.f32.bf16.bf16.f32 "
        "{%0,%1,%2,%3},{%4,%5,%6,%7},{%8,%9},{%0,%1,%2,%3};"
        : "+f"(c0),"+f"(c1),"+f"(c2),"+f"(c3)
        : "r"(a0),"r"(a1),"r"(a2),"r"(a3),"r"(b0),"r"(b1));
}

__device__ __forceinline__ void split2(float lo, float hi, unsigned &b, unsigned &r)
{
    asm("cvt.rn.bf16x2.f32 %0, %1, %2;" : "=r"(b) : "f"(hi), "f"(lo));
    __nv_bfloat162 h2 = *reinterpret_cast<__nv_bfloat162*>(&b);
    float blo = __bfloat162float(h2.x);
    float bhi = __bfloat162float(h2.y);
    asm("cvt.rn.bf16x2.f32 %0, %1, %2;" : "=r"(r) : "f"(hi-bhi), "f"(lo-blo));
}

__device__ __forceinline__ unsigned prmtf(unsigned a, unsigned b, unsigned sel)
{
    unsigned d;
    asm("prmt.b32 %0,%1,%2,%3;" : "=r"(d) : "r"(a), "r"(b), "r"(sel));
    return d;
}

__device__ __forceinline__ void cp16(unsigned dst, const void* src)
{
    asm volatile("cp.async.cg.shared.global [%0],[%1],16;" :: "r"(dst), "l"(src));
}
__device__ __forceinline__ unsigned smem_u32(const void* p)
{
    unsigned a;
    asm("{.reg .u64 t; cvta.to.shared.u64 t, %1; cvt.u32.u64 %0, t;}" : "=r"(a) : "l"(p));
    return a;
}

// ---------------------------------------------------------------------------
// Kernel 1: QKV projection (split-bf16 mma), emits pre-split frag-ordered planes.
// grid (3, MT/128), block 256 (8 warps x 16 rows).
// ---------------------------------------------------------------------------
#define QKV_SMEM ((128*2 + 64*2) * PCH * 4)   // 61440 B

__global__ __launch_bounds__(256) void qkv_kernel(
    const float* __restrict__ x,
    const float* __restrict__ Wk, const float* __restrict__ bk,
    const float* __restrict__ Wq, const float* __restrict__ bq,
    const float* __restrict__ Wv, const float* __restrict__ bv)
{
    extern __shared__ unsigned smu[];
    unsigned* Xb = smu;
    unsigned* Xr = Xb + 128*PCH;
    unsigned* Wb = Xr + 128*PCH;
    unsigned* Wr = Wb + 64*PCH;

    const int mat = blockIdx.x;
    const float* W; const float* bias;
    if (mat == 0)      { W = Wk; bias = bk; }
    else if (mat == 1) { W = Wq; bias = bq; }
    else               { W = Wv; bias = bv; }

    const int m0   = blockIdx.y * 128;
    const int tid  = threadIdx.x;
    const int lane = tid & 31;
    const int g    = lane >> 2;
    const int q    = lane & 3;
    const int wrow = (tid >> 5) * 16;

    float acc[8][4];
    #pragma unroll
    for (int j = 0; j < 8; j++)
        #pragma unroll
        for (int c = 0; c < 4; c++) acc[j][c] = 0.f;

    for (int kc = 0; kc < DIN; kc += 64) {
        __syncthreads();
        #pragma unroll
        for (int i = 0; i < 8; i++) {
            int idx = tid + 256*i;
            int row = idx >> 4, c4 = idx & 15;
            float4 v = *(const float4*)&x[(size_t)(m0+row)*DIN + kc + c4*4];
            unsigned b0,r0,b1,r1;
            split2(v.x, v.y, b0, r0);
            split2(v.z, v.w, b1, r1);
            int s0 = slotf(2*c4), s1 = slotf(2*c4+1);
            Xb[row*PCH+s0] = b0;  Xb[row*PCH+s1] = b1;
            Xr[row*PCH+s0] = r0;  Xr[row*PCH+s1] = r1;
        }
        #pragma unroll
        for (int i = 0; i < 4; i++) {
            int idx = tid + 256*i;
            int row = idx >> 4, c4 = idx & 15;
            float4 v = *(const float4*)&W[(size_t)row*DIN + kc + c4*4];
            unsigned b0,r0,b1,r1;
            split2(v.x, v.y, b0, r0);
            split2(v.z, v.w, b1, r1);
            int s0 = slotf(2*c4), s1 = slotf(2*c4+1);
            Wb[row*PCH+s0] = b0;  Wb[row*PCH+s1] = b1;
            Wr[row*PCH+s0] = r0;  Wr[row*PCH+s1] = r1;
        }
        __syncthreads();

        #pragma unroll
        for (int ks = 0; ks < 4; ks++) {
            const int a0 = (wrow+g)*PCH + ks*8 + q*2;
            uint2 xAb = *(const uint2*)&Xb[a0];
            uint2 xBb = *(const uint2*)&Xb[a0 + 8*PCH];
            uint2 xAr = *(const uint2*)&Xr[a0];
            uint2 xBr = *(const uint2*)&Xr[a0 + 8*PCH];
            #pragma unroll
            for (int jn = 0; jn < 8; jn++) {
                const int bbo = (jn*8+g)*PCH + ks*8 + q*2;
                uint2 wb = *(const uint2*)&Wb[bbo];
                uint2 wr = *(const uint2*)&Wr[bbo];
                mma16816(acc[jn][0],acc[jn][1],acc[jn][2],acc[jn][3],
                         xAb.x,xBb.x,xAb.y,xBb.y, wb.x,wb.y);
                mma16816(acc[jn][0],acc[jn][1],acc[jn][2],acc[jn][3],
                         xAb.x,xBb.x,xAb.y,xBb.y, wr.x,wr.y);
                mma16816(acc[jn][0],acc[jn][1],acc[jn][2],acc[jn][3],
                         xAr.x,xBr.x,xAr.y,xBr.y, wb.x,wb.y);
            }
        }
    }

    // epilogue: bias + relu, pre-split store
    const float qscale = (mat == 1) ? 0.125f : 1.0f;  // fold 1/sqrt(64) into Q
    #pragma unroll
    for (int jn = 0; jn < 8; jn++) {
        int col = jn*8 + q*2;
        float2 bb = *(const float2*)&bias[col];
        float o0 = fmaxf(acc[jn][0]+bb.x, 0.f) * qscale;
        float o1 = fmaxf(acc[jn][1]+bb.y, 0.f) * qscale;
        float o2 = fmaxf(acc[jn][2]+bb.x, 0.f) * qscale;
        float o3 = fmaxf(acc[jn][3]+bb.y, 0.f) * qscale;
        unsigned vb0, vr0, vb1, vr1;
        split2(o0, o1, vb0, vr0);   // row r0
        split2(o2, o3, vb1, vr1);   // row r0+8

        if (mat != 2) {
            unsigned* pb = (mat == 0) ? g_kb : g_qb;
            unsigned* pr = (mat == 0) ? g_kr : g_qr;
            int sl = slotf(jn*4 + q);
            size_t r0 = (size_t)(m0 + wrow + g);
            pb[r0*32 + sl]     = vb0;  pr[r0*32 + sl]     = vr0;
            pb[(r0+8)*32 + sl] = vb1;  pr[(r0+8)*32 + sl] = vr1;
        } else {
            // V: transpose to key-pair u32s via shfl(4)+prmt, frag-ordered per tile
            unsigned ob0 = __shfl_xor_sync(0xffffffffu, vb0, 4);
            unsigned or0 = __shfl_xor_sync(0xffffffffu, vr0, 4);
            unsigned ob1 = __shfl_xor_sync(0xffffffffu, vb1, 4);
            unsigned or1 = __shfl_xor_sync(0xffffffffu, vr1, 4);
            unsigned rb0, rr0, rb1, rr1;
            if ((g & 1) == 0) {   // this lane holds the even key -> emit column q*2
                rb0 = prmtf(vb0, ob0, 0x5410); rr0 = prmtf(vr0, or0, 0x5410);
                rb1 = prmtf(vb1, ob1, 0x5410); rr1 = prmtf(vr1, or1, 0x5410);
            } else {              // odd key -> emit column q*2+1
                rb0 = prmtf(ob0, vb0, 0x7632); rr0 = prmtf(or0, vr0, 0x7632);
                rb1 = prmtf(ob1, vb1, 0x7632); rr1 = prmtf(or1, vr1, 0x7632);
            }
            int d     = jn*8 + q*2 + (g & 1);
            int brow  = m0 / T;
            int base0 = (m0 & (T-1)) + wrow + (g & ~1);  // even local key, first row
            int tile  = base0 >> 6;
            int p0    = (base0 & 63) >> 1;
            size_t idx0 = ((size_t)(brow*64 + d))*(T/2) + tile*32 + slotf(p0);
            size_t idx1 = ((size_t)(brow*64 + d))*(T/2) + tile*32 + slotf(p0 + 4);
            g_vtb[idx0] = rb0;  g_vtr[idx0] = rr0;
            g_vtb[idx1] = rb1;  g_vtr[idx1] = rr1;
        }
    }
}

// ---------------------------------------------------------------------------
// Kernel 2: flash attention. Q frags in registers; K/V pre-split bf16 via
// cp.async double-buffered pipeline; LDS.64 fragment loads.
// grid (T/128, B), block 256.
// ---------------------------------------------------------------------------
#define ASTAGE (4*64*PCH)               // u32 per stage
#define ATTN_SMEM (2*ASTAGE*4)          // 81920 B

__global__ __launch_bounds__(256) void attn_kernel(float* __restrict__ out)
{
    extern __shared__ unsigned smu[];
    const unsigned sbase = smem_u32(smu);

    const int b    = blockIdx.y;
    const int q0   = blockIdx.x * 128;
    const int tid  = threadIdx.x;
    const int lane = tid & 31;
    const int g    = lane >> 2;
    const int q    = lane & 3;
    const int wrow = (tid >> 5) * 16;

    // cp.async role: arr = K_b / K_r / Vt_b / Vt_r ; one 128B row per thread
    const int arr = tid >> 6;        // 0..3
    const int row = tid & 63;        // 0..63
    const unsigned* src0;
    int tstep;                        // u32 advance per 64-key tile
    if      (arr == 0) { src0 = g_kb  + ((size_t)(b*T) + row)*32;     tstep = 32; }
    else if (arr == 1) { src0 = g_kr  + ((size_t)(b*T) + row)*32;     tstep = 32; }
    else if (arr == 2) { src0 = g_vtb + ((size_t)(b*64 + row))*(T/2); tstep = 32; }
    else               { src0 = g_vtr + ((size_t)(b*64 + row))*(T/2); tstep = 32; }
    const unsigned dstoff = (unsigned)(arr*64*PCH + row*PCH) * 4u;

    #define ISSUE(kt, stg) do {                                                 \
        const unsigned* s_ = src0 + (size_t)((kt)/64) * 64 * tstep / 2 * 0;     \
        const unsigned* sp_ = (arr < 2) ? (src0 + (size_t)(kt)*32)              \
                                        : (src0 + (size_t)(kt)/2);              \
        unsigned d_ = sbase + (unsigned)(stg)*ASTAGE*4u + dstoff;               \
        _Pragma("unroll")                                                        \
        for (int i_ = 0; i_ < 8; i_++) cp16(d_ + i_*16u, sp_ + i_*4);           \
        (void)s_;                                                                \
    } while (0)

    // Q fragments -> registers (loop-invariant)
    unsigned qb0[4],qb1[4],qb2[4],qb3[4], qr0[4],qr1[4],qr2[4],qr3[4];
    {
        const size_t r0 = (size_t)(b*T + q0 + wrow + g);
        // kick off first K/V tile before the Q LDGs
        ISSUE(0, 0);
        asm volatile("cp.async.commit_group;");
        #pragma unroll
        for (int ks = 0; ks < 4; ks++) {
            uint2 a  = *(const uint2*)&g_qb[r0*32     + ks*8 + q*2];
            uint2 c  = *(const uint2*)&g_qb[(r0+8)*32 + ks*8 + q*2];
            qb0[ks]=a.x; qb2[ks]=a.y; qb1[ks]=c.x; qb3[ks]=c.y;
            uint2 ar = *(const uint2*)&g_qr[r0*32     + ks*8 + q*2];
            uint2 cr = *(const uint2*)&g_qr[(r0+8)*32 + ks*8 + q*2];
            qr0[ks]=ar.x; qr2[ks]=ar.y; qr1[ks]=cr.x; qr3[ks]=cr.y;
        }
    }

    float oacc[8][4];
    #pragma unroll
    for (int j = 0; j < 8; j++)
        #pragma unroll
        for (int c = 0; c < 4; c++) oacc[j][c] = 0.f;
    float m0 = -1e30f, m1 = -1e30f, l0 = 0.f, l1 = 0.f;

    int stg = 0;
    for (int kt = 0; kt < T; kt += 64) {
        if (kt + 64 < T) ISSUE(kt + 64, stg ^ 1);
        asm volatile("cp.async.commit_group;");
        asm volatile("cp.async.wait_group 1;");
        __syncthreads();

        unsigned* Kb = smu + stg*ASTAGE;
        unsigned* Kr = Kb + 64*PCH;
        unsigned* Vb = Kb + 128*PCH;
        unsigned* Vr = Kb + 192*PCH;

        // S = Q K^T  (bb + br + rb)
        float s[8][4];
        #pragma unroll
        for (int j = 0; j < 8; j++)
            #pragma unroll
            for (int c = 0; c < 4; c++) s[j][c] = 0.f;

        #pragma unroll
        for (int ks = 0; ks < 4; ks++) {
            #pragma unroll
            for (int jn = 0; jn < 8; jn++) {
                const int bbo = (jn*8+g)*PCH + ks*8 + q*2;
                uint2 kb = *(const uint2*)&Kb[bbo];
                uint2 kr = *(const uint2*)&Kr[bbo];
                mma16816(s[jn][0],s[jn][1],s[jn][2],s[jn][3],
                         qb0[ks],qb1[ks],qb2[ks],qb3[ks], kb.x,kb.y);
                mma16816(s[jn][0],s[jn][1],s[jn][2],s[jn][3],
                         qb0[ks],qb1[ks],qb2[ks],qb3[ks], kr.x,kr.y);
                mma16816(s[jn][0],s[jn][1],s[jn][2],s[jn][3],
                         qr0[ks],qr1[ks],qr2[ks],qr3[ks], kb.x,kb.y);
            }
        }

        // online softmax
        float mx0 = -1e30f, mx1 = -1e30f;
        #pragma unroll
        for (int j = 0; j < 8; j++) {
            mx0 = fmaxf(mx0, fmaxf(s[j][0], s[j][1]));
            mx1 = fmaxf(mx1, fmaxf(s[j][2], s[j][3]));
        }
        mx0 = fmaxf(mx0, __shfl_xor_sync(0xffffffffu, mx0, 1));
        mx0 = fmaxf(mx0, __shfl_xor_sync(0xffffffffu, mx0, 2));
        mx1 = fmaxf(mx1, __shfl_xor_sync(0xffffffffu, mx1, 1));
        mx1 = fmaxf(mx1, __shfl_xor_sync(0xffffffffu, mx1, 2));
        float mn0 = fmaxf(m0, mx0), mn1 = fmaxf(m1, mx1);
        float al0 = __expf(m0 - mn0), al1 = __expf(m1 - mn1);
        m0 = mn0; m1 = mn1;

        float sum0 = 0.f, sum1 = 0.f;
        #pragma unroll
        for (int j = 0; j < 8; j++) {
            s[j][0] = __expf(s[j][0] - mn0);
            s[j][1] = __expf(s[j][1] - mn0);
            s[j][2] = __expf(s[j][2] - mn1);
            s[j][3] = __expf(s[j][3] - mn1);
            sum0 += s[j][0] + s[j][1];
            sum1 += s[j][2] + s[j][3];
        }
        sum0 += __shfl_xor_sync(0xffffffffu, sum0, 1);
        sum0 += __shfl_xor_sync(0xffffffffu, sum0, 2);
        sum1 += __shfl_xor_sync(0xffffffffu, sum1, 1);
        sum1 += __shfl_xor_sync(0xffffffffu, sum1, 2);
        l0 = l0*al0 + sum0;
        l1 = l1*al1 + sum1;
        #pragma unroll
        for (int j = 0; j < 8; j++) {
            oacc[j][0]*=al0; oacc[j][1]*=al0; oacc[j][2]*=al1; oacc[j][3]*=al1;
        }

        // O += P V
        #pragma unroll
        for (int kp = 0; kp < 4; kp++) {
            unsigned pb0,pr0,pb1,pr1,pb2,pr2,pb3,pr3;
            split2(s[2*kp  ][0], s[2*kp  ][1], pb0, pr0);
            split2(s[2*kp  ][2], s[2*kp  ][3], pb1, pr1);
            split2(s[2*kp+1][0], s[2*kp+1][1], pb2, pr2);
            split2(s[2*kp+1][2], s[2*kp+1][3], pb3, pr3);
            #pragma unroll
            for (int jn = 0; jn < 8; jn++) {
                const int vbo = (jn*8+g)*PCH + kp*8 + q*2;
                uint2 vb = *(const uint2*)&Vb[vbo];
                uint2 vr = *(const uint2*)&Vr[vbo];
                mma16816(oacc[jn][0],oacc[jn][1],oacc[jn][2],oacc[jn][3],
                         pb0,pb1,pb2,pb3, vb.x,vb.y);
                mma16816(oacc[jn][0],oacc[jn][1],oacc[jn][2],oacc[jn][3],
                         pb0,pb1,pb2,pb3, vr.x,vr.y);
                mma16816(oacc[jn][0],oacc[jn][1],oacc[jn][2],oacc[jn][3],
                         pr0,pr1,pr2,pr3, vb.x,vb.y);
            }
        }
        __syncthreads();
        stg ^= 1;
    }

    float inv0 = 1.f / l0, inv1 = 1.f / l1;
    float* Og = out + ((size_t)b*T + q0)*DHEAD;
    #pragma unroll
    for (int jn = 0; jn < 8; jn++) {
        int col = jn*8 + q*2;
        int r0 = wrow + g;
        float2 o0 = make_float2(oacc[jn][0]*inv0, oacc[jn][1]*inv0);
        float2 o1 = make_float2(oacc[jn][2]*inv1, oacc[jn][3]*inv1);
        *(float2*)&Og[(size_t)r0*DHEAD + col]     = o0;
        *(float2*)&Og[(size_t)(r0+8)*DHEAD + col] = o1;
    }
    #undef ISSUE
}

// ---------------------------------------------------------------------------
extern "C" void kernel_launch(void* const* d_in, const int* in_sizes, int n_in,
                              void* d_out, int out_size)
{
    const float* x  = (const float*)d_in[0];
    const float* Wk = (const float*)d_in[1];
    const float* bk = (const float*)d_in[2];
    const float* Wq = (const float*)d_in[3];
    const float* bq = (const float*)d_in[4];
    const float* Wv = (const float*)d_in[5];
    const float* bv = (const float*)d_in[6];
    float* out = (float*)d_out;

    cudaFuncSetAttribute(qkv_kernel,
                         cudaFuncAttributeMaxDynamicSharedMemorySize, QKV_SMEM);
    cudaFuncSetAttribute(attn_kernel,
                         cudaFuncAttributeMaxDynamicSharedMemorySize, ATTN_SMEM);

    dim3 g1(3, MT / 128);
    qkv_kernel<<<g1, 256, QKV_SMEM>>>(x, Wk, bk, Wq, bq, Wv, bv);

    dim3 g2(T / 128, NB);
    attn_kernel<<<g2, 256, ATTN_SMEM>>>(out);
}